// round 3
// baseline (speedup 1.0000x reference)
#include <cuda_runtime.h>
#include <math.h>
#include <stdint.h>

// Problem constants (worst-case sizing for static scratch)
#define MAXB 8
#define MAXS 8192
#define MAXH 768
#define MAXBS (MAXB * MAXS)          // 65536 rows

// ---------------- static device scratch (no allocations allowed) -------------
__device__ float g_act[(size_t)MAXBS * MAXH];        // silu activations, (B*L, H) row-major (~201 MB)
__device__ int   g_tapPos[(size_t)MAXH * MAXS];      // sparse kernel taps per h (~25 MB)
__device__ float g_tapVal[(size_t)MAXH * MAXS];      // tap values (~25 MB)
__device__ int   g_tapCnt[MAXH];

#define LAM 0.1f

// ---------------- 1) threshold kernel -> sparse tap lists --------------------
// one block per h; the count is owned by this block only, so zero+build in one kernel.
__global__ void build_taps_kernel(const float* __restrict__ kern, int L) {
    int h = blockIdx.x;
    if (threadIdx.x == 0) g_tapCnt[h] = 0;
    __syncthreads();
    const float* kr = kern + (size_t)h * L;
    for (int j = threadIdx.x; j < L; j += blockDim.x) {
        float kv = kr[j];
        float a = fabsf(kv) - LAM;
        if (a > 0.0f) {
            float val = copysignf(a, kv);   // relu(|k|-lam)*sign(k)
            int idx = atomicAdd(&g_tapCnt[h], 1);
            g_tapPos[(size_t)h * L + idx] = j;
            g_tapVal[(size_t)h * L + idx] = val;
        }
    }
}

// ---------------- 2) activation: sparse causal conv + skip + silu ------------
// act[b*L + l, h] = silu( x[b,l,h]*D[h] + sum_taps k[h,j]*x[b,l-j,h] )
__global__ void act_kernel(const float* __restrict__ x, const float* __restrict__ D,
                           float* __restrict__ act, int total, int H, int S) {
    int idx = blockIdx.x * blockDim.x + threadIdx.x;
    if (idx >= total) return;
    int h  = idx % H;
    int bl = idx / H;
    float v = x[idx] * D[h];
    int cnt = g_tapCnt[h];
    if (cnt > 0) {
        int l = bl % S;
        int b = bl / S;
        const float* xb = x + (size_t)b * S * H;
        const int*   tp = g_tapPos + (size_t)h * S;
        const float* tv = g_tapVal + (size_t)h * S;
        for (int t = 0; t < cnt; t++) {
            int j = tp[t];
            if (j <= l) v += tv[t] * xb[(size_t)(l - j) * H + h];
        }
    }
    act[idx] = v / (1.0f + expf(-v));   // silu
}

// ---------------- 3) fused GEMM + GLU + residual -----------------------------
// A: (M,K) row-major = g_act ; W: (2H,K) row-major ; out: (M,H) row-major
// block computes rows [m0,m0+128) x cols [n0,n0+64) of BOTH GLU halves:
//   a = A @ W[n0+c]^T + bias[n0+c],  g = A @ W[H+n0+c]^T + bias[H+n0+c]
//   out = a * sigmoid(g) + x
#define BM 128
#define BN 64
#define BK 16
#define TM 8
#define TN 4

__global__ __launch_bounds__(256, 2)
void gemm_glu_kernel(const float* __restrict__ A, const float* __restrict__ W,
                     const float* __restrict__ bias, const float* __restrict__ x,
                     float* __restrict__ out, int M, int H, int K) {
    __shared__ float As[BK][BM];
    __shared__ float Ba[BK][BN];
    __shared__ float Bg[BK][BN];

    const int tid = threadIdx.x;
    const int tx  = tid & 15;          // 0..15 -> n micro (TN=4 -> 64 cols)
    const int ty  = tid >> 4;          // 0..15 -> m micro (TM=8 -> 128 rows)
    const int m0  = blockIdx.y * BM;
    const int n0  = blockIdx.x * BN;

    float acc_a[TM][TN], acc_g[TM][TN];
    #pragma unroll
    for (int i = 0; i < TM; i++)
        #pragma unroll
        for (int j = 0; j < TN; j++) { acc_a[i][j] = 0.0f; acc_g[i][j] = 0.0f; }

    const float* Wa = W + (size_t)n0 * K;         // rows n0..n0+63
    const float* Wg = W + (size_t)(H + n0) * K;   // rows H+n0..H+n0+63

    for (int k0 = 0; k0 < K; k0 += BK) {
        // A tile: 128 rows x 16 k = 512 float4 -> 2 per thread
        #pragma unroll
        for (int i = 0; i < 2; i++) {
            int q   = tid + i * 256;
            int row = q >> 2;
            int kq  = (q & 3) * 4;
            float4 v = *(const float4*)(A + (size_t)(m0 + row) * K + k0 + kq);
            As[kq + 0][row] = v.x; As[kq + 1][row] = v.y;
            As[kq + 2][row] = v.z; As[kq + 3][row] = v.w;
        }
        // Ba / Bg tiles: 64 rows x 16 k = 256 float4 each -> 1 per thread each
        {
            int row = tid >> 2;
            int kq  = (tid & 3) * 4;
            float4 va = *(const float4*)(Wa + (size_t)row * K + k0 + kq);
            Ba[kq + 0][row] = va.x; Ba[kq + 1][row] = va.y;
            Ba[kq + 2][row] = va.z; Ba[kq + 3][row] = va.w;
            float4 vg = *(const float4*)(Wg + (size_t)row * K + k0 + kq);
            Bg[kq + 0][row] = vg.x; Bg[kq + 1][row] = vg.y;
            Bg[kq + 2][row] = vg.z; Bg[kq + 3][row] = vg.w;
        }
        __syncthreads();

        #pragma unroll
        for (int kk = 0; kk < BK; kk++) {
            float4 a0 = *(const float4*)&As[kk][ty * 8];
            float4 a1 = *(const float4*)&As[kk][ty * 8 + 4];
            float av[8] = {a0.x, a0.y, a0.z, a0.w, a1.x, a1.y, a1.z, a1.w};
            float4 b0 = *(const float4*)&Ba[kk][tx * 4];
            float4 g0 = *(const float4*)&Bg[kk][tx * 4];
            float bva[4] = {b0.x, b0.y, b0.z, b0.w};
            float bvg[4] = {g0.x, g0.y, g0.z, g0.w};
            #pragma unroll
            for (int i = 0; i < TM; i++)
                #pragma unroll
                for (int j = 0; j < TN; j++) {
                    acc_a[i][j] = fmaf(av[i], bva[j], acc_a[i][j]);
                    acc_g[i][j] = fmaf(av[i], bvg[j], acc_g[i][j]);
                }
        }
        __syncthreads();
    }

    // epilogue: bias + GLU + residual
    const int c0 = n0 + tx * 4;
    float ba0 = bias[c0 + 0], ba1 = bias[c0 + 1], ba2 = bias[c0 + 2], ba3 = bias[c0 + 3];
    float bg0 = bias[H + c0 + 0], bg1 = bias[H + c0 + 1],
          bg2 = bias[H + c0 + 2], bg3 = bias[H + c0 + 3];
    #pragma unroll
    for (int i = 0; i < TM; i++) {
        int m = m0 + ty * 8 + i;
        const float* xr = x + (size_t)m * H + c0;
        float4 xv = *(const float4*)xr;
        float a0 = acc_a[i][0] + ba0, g0 = acc_g[i][0] + bg0;
        float a1 = acc_a[i][1] + ba1, g1 = acc_g[i][1] + bg1;
        float a2 = acc_a[i][2] + ba2, g2 = acc_g[i][2] + bg2;
        float a3 = acc_a[i][3] + ba3, g3 = acc_g[i][3] + bg3;
        float4 o;
        o.x = a0 / (1.0f + expf(-g0)) + xv.x;
        o.y = a1 / (1.0f + expf(-g1)) + xv.y;
        o.z = a2 / (1.0f + expf(-g2)) + xv.z;
        o.w = a3 / (1.0f + expf(-g3)) + xv.w;
        *(float4*)(out + (size_t)m * H + c0) = o;
    }
}

// ---------------- launch ------------------------------------------------------
extern "C" void kernel_launch(void* const* d_in, const int* in_sizes, int n_in,
                              void* d_out, int out_size) {
    const float* x    = (const float*)d_in[0];   // (B, S, H)
    const float* kern = (const float*)d_in[1];   // (1, H, S)
    const float* D    = (const float*)d_in[2];   // (1, H)
    const float* W    = (const float*)d_in[3];   // (2H, H)
    const float* bias = (const float*)d_in[4];   // (2H,)
    float* out        = (float*)d_out;

    const int H  = in_sizes[2];                  // 768
    const int S  = in_sizes[1] / H;              // 8192
    const int M  = in_sizes[0] / H;              // B*S = 65536
    const int K  = H;
    const int total = M * H;

    float* act; cudaGetSymbolAddress((void**)&act, g_act);

    // 1) sparse taps from thresholded kernel
    build_taps_kernel<<<H, 256>>>(kern, S);

    // 2) conv(+skip)+silu activations
    act_kernel<<<(total + 255) / 256, 256>>>(x, D, act, total, H, S);

    // 3) fused GEMM + GLU + residual -> out
    dim3 grid(H / BN, M / BM);
    gemm_glu_kernel<<<grid, 256>>>(act, W, bias, x, out, M, H, K);
}

// round 6
// speedup vs baseline: 2.5454x; 2.5454x over previous
#include <cuda_runtime.h>
#include <math.h>
#include <stdint.h>

// Problem worst-case sizing
#define MAXB 8
#define MAXS 8192
#define MAXH 768
#define MAXBS (MAXB * MAXS)          // 65536 rows

// ---------------- static device scratch ----------------
__device__ float g_act[(size_t)MAXBS * MAXH];        // tf32-rounded silu activations (~201 MB)
__device__ float g_wr[(size_t)(2 * MAXH) * MAXH];    // tf32-rounded W (~4.7 MB)
__device__ int   g_tapPos[(size_t)MAXH * MAXS];
__device__ float g_tapVal[(size_t)MAXH * MAXS];
__device__ int   g_tapCnt[MAXH];

#define LAM 0.1f

__device__ __forceinline__ uint32_t to_tf32(float f) {
    uint32_t r;
    asm("cvt.rna.tf32.f32 %0, %1;" : "=r"(r) : "f"(f));
    return r;
}

#define CP_ASYNC16(dst, src) \
    asm volatile("cp.async.cg.shared.global [%0], [%1], 16;" :: "r"(dst), "l"(src) : "memory")

__device__ __forceinline__ uint32_t smem_u32(const void* p) {
    uint32_t a;
    asm("{ .reg .u64 t; cvta.to.shared.u64 t, %1; cvt.u32.u64 %0, t; }" : "=r"(a) : "l"(p));
    return a;
}

// mma.sync m16n8k8 tf32, fp32 accum
#define MMA_TF32(c, a, b0, b1)                                                  \
    asm volatile(                                                               \
        "mma.sync.aligned.m16n8k8.row.col.f32.tf32.tf32.f32 "                   \
        "{%0,%1,%2,%3}, {%4,%5,%6,%7}, {%8,%9}, {%0,%1,%2,%3};"                 \
        : "+f"((c)[0]), "+f"((c)[1]), "+f"((c)[2]), "+f"((c)[3])                \
        : "r"((a)[0]), "r"((a)[1]), "r"((a)[2]), "r"((a)[3]),                   \
          "r"(b0), "r"(b1))

// ---------------- 1) threshold kernel -> sparse tap lists --------------------
__global__ void build_taps_kernel(const float* __restrict__ kern, int L) {
    int h = blockIdx.x;
    if (threadIdx.x == 0) g_tapCnt[h] = 0;
    __syncthreads();
    const float* kr = kern + (size_t)h * L;
    for (int j = threadIdx.x; j < L; j += blockDim.x) {
        float kv = kr[j];
        float a = fabsf(kv) - LAM;
        if (a > 0.0f) {
            float val = copysignf(a, kv);
            int idx = atomicAdd(&g_tapCnt[h], 1);
            g_tapPos[(size_t)h * L + idx] = j;
            g_tapVal[(size_t)h * L + idx] = val;
        }
    }
}

// ---------------- 1b) tf32-round W ----------------
__global__ void round_w_kernel(const float* __restrict__ W, float* __restrict__ Wr, int n) {
    int i = blockIdx.x * blockDim.x + threadIdx.x;
    if (i < n) Wr[i] = __uint_as_float(to_tf32(W[i]));
}

// ---------------- 2) activation: sparse conv + skip + silu, tf32-rounded -----
__global__ void act_kernel(const float* __restrict__ x, const float* __restrict__ D,
                           float* __restrict__ act, int total4, int H, int S) {
    int i = blockIdx.x * blockDim.x + threadIdx.x;
    if (i >= total4) return;
    int base = i * 4;
    int h  = base % H;
    int bl = base / H;
    float4 xv = *(const float4*)(x + base);
    float4 dv = *(const float4*)(D + h);
    float v[4] = {xv.x * dv.x, xv.y * dv.y, xv.z * dv.z, xv.w * dv.w};
    int cnt[4] = {g_tapCnt[h], g_tapCnt[h + 1], g_tapCnt[h + 2], g_tapCnt[h + 3]};
    if (cnt[0] | cnt[1] | cnt[2] | cnt[3]) {
        int l = bl % S;
        int b = bl / S;
        const float* xb = x + (size_t)b * S * H;
        #pragma unroll
        for (int q = 0; q < 4; q++) {
            const int*   tp = g_tapPos + (size_t)(h + q) * S;
            const float* tv = g_tapVal + (size_t)(h + q) * S;
            for (int t = 0; t < cnt[q]; t++) {
                int j = tp[t];
                if (j <= l) v[q] += tv[t] * xb[(size_t)(l - j) * H + h + q];
            }
        }
    }
    float4 o;
    o.x = __uint_as_float(to_tf32(v[0] / (1.0f + expf(-v[0]))));
    o.y = __uint_as_float(to_tf32(v[1] / (1.0f + expf(-v[1]))));
    o.z = __uint_as_float(to_tf32(v[2] / (1.0f + expf(-v[2]))));
    o.w = __uint_as_float(to_tf32(v[3] / (1.0f + expf(-v[3]))));
    *(float4*)(act + base) = o;
}

// ---------------- 3) tf32 mma.sync GEMM + GLU + residual ---------------------
// CTA: 256 M-rows x 64 out-cols. B tile = 128 rows, interleaved: row j even ->
// Wa[n0+j/2], odd -> Wg[n0+j/2]. 512 threads = 16 warps (8 m x 2 n); each warp
// computes 32 rows x 64 B-rows (= 32 out-cols, GLU pairs thread-local).
#define CTA_M 256
#define CTA_C 64                     // output columns per CTA
#define KC    32                     // K-chunk (32 floats = 128 B/row)
#define ABUF_BYTES (CTA_M * KC * 4)              // 32 KB
#define BBUF_BYTES (2 * CTA_C * KC * 4)          // 16 KB
#define BUF_BYTES  (ABUF_BYTES + BBUF_BYTES)     // 48 KB
#define SMEM_GEMM  (2 * BUF_BYTES)               // 96 KB

// swizzled float index inside a [rows][32] tile
__device__ __forceinline__ int sidx(int r, int k) {
    return r * 32 + ((((k >> 2) ^ (r & 7)) << 2) | (k & 3));
}

__global__ __launch_bounds__(512, 1)
void gemm_glu_mma(const float* __restrict__ A, const float* __restrict__ W,
                  const float* __restrict__ bias, const float* __restrict__ x,
                  float* __restrict__ out, int M, int Hd, int K) {
    extern __shared__ float smem[];
    const uint32_t sb = smem_u32(smem);
    const int tid = threadIdx.x;
    const int wid = tid >> 5, lane = tid & 31;
    const int lq = lane >> 2, lr = lane & 3;
    const int warp_m = wid >> 1, warp_n = wid & 1;
    const int m0 = blockIdx.y * CTA_M;
    const int n0 = blockIdx.x * CTA_C;
    const int NCH = K / KC;                      // 24

    float acc[2][8][4];
    #pragma unroll
    for (int tm = 0; tm < 2; tm++)
        #pragma unroll
        for (int tn = 0; tn < 8; tn++)
            #pragma unroll
            for (int q = 0; q < 4; q++) acc[tm][tn][q] = 0.0f;

    auto load_chunk = [&](int c, int buf) {
        const uint32_t ab = sb + buf * BUF_BYTES;
        const uint32_t bb = ab + ABUF_BYTES;
        const int k0 = c * KC;
        // A: 256 rows x 8 granules = 2048 -> 4/thread
        #pragma unroll
        for (int t = 0; t < 4; t++) {
            int idx = tid + t * 512;
            int row = idx >> 3, g = idx & 7;
            CP_ASYNC16(ab + row * 128 + ((g ^ (row & 7)) << 4),
                       A + (size_t)(m0 + row) * K + k0 + g * 4);
        }
        // B: 128 rows x 8 granules = 1024 -> 2/thread; interleaved a/g rows
        #pragma unroll
        for (int t = 0; t < 2; t++) {
            int idx = tid + t * 512;
            int row = idx >> 3, g = idx & 7;
            int wrow = ((row & 1) ? Hd : 0) + n0 + (row >> 1);
            CP_ASYNC16(bb + row * 128 + ((g ^ (row & 7)) << 4),
                       W + (size_t)wrow * K + k0 + g * 4);
        }
        asm volatile("cp.async.commit_group;" ::: "memory");
    };

    load_chunk(0, 0);

    for (int c = 0; c < NCH; c++) {
        const int buf = c & 1;
        if (c + 1 < NCH) {
            load_chunk(c + 1, buf ^ 1);
            asm volatile("cp.async.wait_group 1;" ::: "memory");
        } else {
            asm volatile("cp.async.wait_group 0;" ::: "memory");
        }
        __syncthreads();

        const float* As = smem + buf * (BUF_BYTES / 4);
        const float* Bs = As + (ABUF_BYTES / 4);
        #pragma unroll
        for (int ks = 0; ks < 4; ks++) {
            const int kb = ks * 8 + lr;
            uint32_t af[2][4];
            #pragma unroll
            for (int tm = 0; tm < 2; tm++) {
                const int rA = warp_m * 32 + tm * 16 + lq;
                af[tm][0] = __float_as_uint(As[sidx(rA,     kb)]);
                af[tm][1] = __float_as_uint(As[sidx(rA + 8, kb)]);
                af[tm][2] = __float_as_uint(As[sidx(rA,     kb + 4)]);
                af[tm][3] = __float_as_uint(As[sidx(rA + 8, kb + 4)]);
            }
            #pragma unroll
            for (int tn = 0; tn < 8; tn++) {
                const int nrow = warp_n * 64 + tn * 8 + lq;
                uint32_t b0 = __float_as_uint(Bs[sidx(nrow, kb)]);
                uint32_t b1 = __float_as_uint(Bs[sidx(nrow, kb + 4)]);
                MMA_TF32(acc[0][tn], af[0], b0, b1);
                MMA_TF32(acc[1][tn], af[1], b0, b1);
            }
        }
        __syncthreads();
    }

    // epilogue: GLU pairs are (c0,c1) and (c2,c3) within each accumulator tile
    #pragma unroll
    for (int tm = 0; tm < 2; tm++) {
        const int mrow = m0 + warp_m * 32 + tm * 16 + lq;
        #pragma unroll
        for (int tn = 0; tn < 8; tn++) {
            const int col = n0 + warp_n * 32 + tn * 4 + lr;
            const float ba = bias[col], bg = bias[Hd + col];
            {
                float a = acc[tm][tn][0] + ba;
                float g = acc[tm][tn][1] + bg;
                out[(size_t)mrow * Hd + col] =
                    a / (1.0f + expf(-g)) + x[(size_t)mrow * Hd + col];
            }
            {
                float a = acc[tm][tn][2] + ba;
                float g = acc[tm][tn][3] + bg;
                out[(size_t)(mrow + 8) * Hd + col] =
                    a / (1.0f + expf(-g)) + x[(size_t)(mrow + 8) * Hd + col];
            }
        }
    }
}

// ---------------- launch ------------------------------------------------------
extern "C" void kernel_launch(void* const* d_in, const int* in_sizes, int n_in,
                              void* d_out, int out_size) {
    const float* x    = (const float*)d_in[0];   // (B, S, H)
    const float* kern = (const float*)d_in[1];   // (1, H, S)
    const float* D    = (const float*)d_in[2];   // (1, H)
    const float* W    = (const float*)d_in[3];   // (2H, H)
    const float* bias = (const float*)d_in[4];   // (2H,)
    float* out        = (float*)d_out;

    const int H  = in_sizes[2];                  // 768
    const int S  = in_sizes[1] / H;              // 8192
    const int M  = in_sizes[0] / H;              // 65536
    const int K  = H;
    const int total = M * H;

    float* act; cudaGetSymbolAddress((void**)&act, g_act);
    float* wr;  cudaGetSymbolAddress((void**)&wr,  g_wr);

    build_taps_kernel<<<H, 256>>>(kern, S);
    round_w_kernel<<<(2 * H * K + 255) / 256, 256>>>(W, wr, 2 * H * K);
    act_kernel<<<(total / 4 + 255) / 256, 256>>>(x, D, act, total / 4, H, S);

    cudaFuncSetAttribute(gemm_glu_mma, cudaFuncAttributeMaxDynamicSharedMemorySize,
                         SMEM_GEMM);
    dim3 grid(H / CTA_C, M / CTA_M);             // (12, 256)
    gemm_glu_mma<<<grid, 512, SMEM_GEMM>>>(act, wr, bias, x, out, M, H, K);
}

// round 10
// speedup vs baseline: 5.3531x; 2.1030x over previous
#include <cuda_runtime.h>
#include <cuda_bf16.h>
#include <math.h>
#include <stdint.h>

// Problem worst-case sizing
#define MAXB 8
#define MAXS 8192
#define MAXH 768
#define MAXBS (MAXB * MAXS)          // 65536 rows

// ---------------- static device scratch ----------------
__device__ __nv_bfloat16 g_actb[(size_t)MAXBS * MAXH];      // bf16 silu activations (~100 MB)
__device__ __nv_bfloat16 g_wb[(size_t)(2 * MAXH) * MAXH];   // bf16 W (~2.4 MB)
__device__ int   g_tapPos[(size_t)MAXH * MAXS];
__device__ float g_tapVal[(size_t)MAXH * MAXS];
__device__ int   g_tapCnt[MAXH];

#define LAM 0.1f

#define CP_ASYNC16(dst, src) \
    asm volatile("cp.async.cg.shared.global [%0], [%1], 16;" :: "r"(dst), "l"(src) : "memory")

__device__ __forceinline__ uint32_t smem_u32(const void* p) {
    uint32_t a;
    asm("{ .reg .u64 t; cvta.to.shared.u64 t, %1; cvt.u32.u64 %0, t; }" : "=r"(a) : "l"(p));
    return a;
}

#define LDSM_X4(r, addr)                                                        \
    asm volatile("ldmatrix.sync.aligned.m8n8.x4.shared.b16 {%0,%1,%2,%3}, [%4];" \
        : "=r"((r)[0]), "=r"((r)[1]), "=r"((r)[2]), "=r"((r)[3]) : "r"(addr))

// mma m16n8k16 bf16, fp32 accum
#define MMA_BF16(c, a, b0, b1)                                                  \
    asm volatile(                                                               \
        "mma.sync.aligned.m16n8k16.row.col.f32.bf16.bf16.f32 "                  \
        "{%0,%1,%2,%3}, {%4,%5,%6,%7}, {%8,%9}, {%0,%1,%2,%3};"                 \
        : "+f"((c)[0]), "+f"((c)[1]), "+f"((c)[2]), "+f"((c)[3])                \
        : "r"((a)[0]), "r"((a)[1]), "r"((a)[2]), "r"((a)[3]),                   \
          "r"(b0), "r"(b1))

// ---------------- 1) threshold kernel -> sparse tap lists --------------------
__global__ void build_taps_kernel(const float* __restrict__ kern, int L) {
    int h = blockIdx.x;
    if (threadIdx.x == 0) g_tapCnt[h] = 0;
    __syncthreads();
    const float* kr = kern + (size_t)h * L;
    for (int j = threadIdx.x; j < L; j += blockDim.x) {
        float kv = kr[j];
        float a = fabsf(kv) - LAM;
        if (a > 0.0f) {
            float val = copysignf(a, kv);
            int idx = atomicAdd(&g_tapCnt[h], 1);
            g_tapPos[(size_t)h * L + idx] = j;
            g_tapVal[(size_t)h * L + idx] = val;
        }
    }
}

// ---------------- 1b) convert W to bf16 ----------------
__global__ void conv_w_kernel(const float* __restrict__ W, __nv_bfloat16* __restrict__ Wb, int n4) {
    int i = blockIdx.x * blockDim.x + threadIdx.x;
    if (i >= n4) return;
    float4 v = *(const float4*)(W + i * 4);
    __nv_bfloat162* o = (__nv_bfloat162*)(Wb + i * 4);
    o[0] = __floats2bfloat162_rn(v.x, v.y);
    o[1] = __floats2bfloat162_rn(v.z, v.w);
}

// ---------------- 2) activation: sparse conv + skip + silu -> bf16 -----------
__global__ void act_kernel(const float* __restrict__ x, const float* __restrict__ D,
                           __nv_bfloat16* __restrict__ act, int total4, int H, int S) {
    int i = blockIdx.x * blockDim.x + threadIdx.x;
    if (i >= total4) return;
    int base = i * 4;
    int h  = base % H;
    int bl = base / H;
    float4 xv = *(const float4*)(x + base);
    float4 dv = *(const float4*)(D + h);
    float v[4] = {xv.x * dv.x, xv.y * dv.y, xv.z * dv.z, xv.w * dv.w};
    int cnt[4] = {g_tapCnt[h], g_tapCnt[h + 1], g_tapCnt[h + 2], g_tapCnt[h + 3]};
    if (cnt[0] | cnt[1] | cnt[2] | cnt[3]) {
        int l = bl % S;
        int b = bl / S;
        const float* xb = x + (size_t)b * S * H;
        #pragma unroll
        for (int q = 0; q < 4; q++) {
            const int*   tp = g_tapPos + (size_t)(h + q) * S;
            const float* tv = g_tapVal + (size_t)(h + q) * S;
            for (int t = 0; t < cnt[q]; t++) {
                int j = tp[t];
                if (j <= l) v[q] += tv[t] * xb[(size_t)(l - j) * H + h + q];
            }
        }
    }
    float o0 = v[0] / (1.0f + expf(-v[0]));
    float o1 = v[1] / (1.0f + expf(-v[1]));
    float o2 = v[2] / (1.0f + expf(-v[2]));
    float o3 = v[3] / (1.0f + expf(-v[3]));
    __nv_bfloat162* op = (__nv_bfloat162*)(act + base);
    op[0] = __floats2bfloat162_rn(o0, o1);
    op[1] = __floats2bfloat162_rn(o2, o3);
}

// ---------------- 3) bf16 mma.sync GEMM + GLU + residual ---------------------
// CTA: 256 M-rows x 64 out-cols. B tile = 128 interleaved rows (even=Wa, odd=Wg).
// 512 threads = 16 warps (8 m x 2 n). Warp: m32 x 64 brows (32 out-cols).
// K-chunk = 64 halves (128 B/row), double-buffered cp.async, ldmatrix feeds.
#define CTA_M 256
#define CTA_C 64
#define KC    64                                   // bf16 halves per chunk
#define ABUF_BYTES (CTA_M * KC * 2)                // 32 KB
#define BBUF_BYTES (2 * CTA_C * KC * 2)            // 16 KB
#define BUF_BYTES  (ABUF_BYTES + BBUF_BYTES)       // 48 KB
#define SMEM_GEMM  (2 * BUF_BYTES)                 // 96 KB

__global__ __launch_bounds__(512, 1)
void gemm_glu_mma(const __nv_bfloat16* __restrict__ A, const __nv_bfloat16* __restrict__ W,
                  const float* __restrict__ bias, const float* __restrict__ x,
                  float* __restrict__ out, int M, int Hd, int K) {
    extern __shared__ char smem[];
    const uint32_t sb = smem_u32(smem);
    const int tid = threadIdx.x;
    const int wid = tid >> 5, lane = tid & 31;
    const int lq = lane >> 2, lr = lane & 3;
    const int warp_m = wid >> 1, warp_n = wid & 1;
    const int m0 = blockIdx.y * CTA_M;
    const int n0 = blockIdx.x * CTA_C;
    const int NCH = K / KC;                        // 12

    float acc[2][8][4];
    #pragma unroll
    for (int tm = 0; tm < 2; tm++)
        #pragma unroll
        for (int tn = 0; tn < 8; tn++)
            #pragma unroll
            for (int q = 0; q < 4; q++) acc[tm][tn][q] = 0.0f;

    // ldmatrix per-lane address components (16B granules, XOR-8 swizzle per row)
    // A x4: lanes 0-7 -> a0 (rows 0-7, gran even), 8-15 -> a1 (rows 8-15),
    //       16-23 -> a2 (rows 0-7, gran odd), 24-31 -> a3
    const int a_rowoff = ((lane >> 3) & 1) * 8 + (lane & 7);
    const int a_gran   = lane >> 4;                // 0/1
    const int a_row    = warp_m * 32 + a_rowoff;   // + tm*16
    const uint32_t a_base0 = (uint32_t)a_row * 128;
    const int a_rsw = a_row & 7;                   // tm*16 doesn't change &7
    // B x4: lanes 0-7 -> b0(tn), 8-15 -> b1(tn), 16-23 -> b0(tn+1), 24-31 -> b1(tn+1)
    const int b_row  = warp_n * 64 + (lane >> 4) * 8 + (lane & 7);  // + tnp*16
    const int b_gran = (lane >> 3) & 1;
    const uint32_t b_base0 = (uint32_t)b_row * 128;
    const int b_rsw = b_row & 7;

    auto load_chunk = [&](int c, int buf) {
        const uint32_t ab = sb + buf * BUF_BYTES;
        const uint32_t bb = ab + ABUF_BYTES;
        const int k0 = c * KC;
        // A: 256 rows x 8 granules = 2048 -> 4/thread
        #pragma unroll
        for (int t = 0; t < 4; t++) {
            int idx = tid + t * 512;
            int row = idx >> 3, g = idx & 7;
            CP_ASYNC16(ab + row * 128 + ((g ^ (row & 7)) << 4),
                       A + (size_t)(m0 + row) * K + k0 + g * 8);
        }
        // B: 128 rows x 8 granules = 1024 -> 2/thread; interleaved a/g rows
        #pragma unroll
        for (int t = 0; t < 2; t++) {
            int idx = tid + t * 512;
            int row = idx >> 3, g = idx & 7;
            int wrow = ((row & 1) ? Hd : 0) + n0 + (row >> 1);
            CP_ASYNC16(bb + row * 128 + ((g ^ (row & 7)) << 4),
                       W + (size_t)wrow * K + k0 + g * 8);
        }
        asm volatile("cp.async.commit_group;" ::: "memory");
    };

    load_chunk(0, 0);

    for (int c = 0; c < NCH; c++) {
        const int buf = c & 1;
        if (c + 1 < NCH) {
            load_chunk(c + 1, buf ^ 1);
            asm volatile("cp.async.wait_group 1;" ::: "memory");
        } else {
            asm volatile("cp.async.wait_group 0;" ::: "memory");
        }
        __syncthreads();

        const uint32_t ab = sb + buf * BUF_BYTES;
        const uint32_t bb = ab + ABUF_BYTES;
        #pragma unroll
        for (int ks = 0; ks < 4; ks++) {           // 4 x k16 per chunk
            uint32_t af[2][4];
            #pragma unroll
            for (int tm = 0; tm < 2; tm++) {
                uint32_t addr = ab + a_base0 + (uint32_t)(tm * 16 * 128)
                              + (uint32_t)((((2 * ks + a_gran) ^ a_rsw)) << 4);
                LDSM_X4(af[tm], addr);
            }
            #pragma unroll
            for (int tnp = 0; tnp < 4; tnp++) {
                uint32_t bf[4];
                uint32_t addr = bb + b_base0 + (uint32_t)(tnp * 16 * 128)
                              + (uint32_t)((((2 * ks + b_gran) ^ b_rsw)) << 4);
                LDSM_X4(bf, addr);
                MMA_BF16(acc[0][2 * tnp],     af[0], bf[0], bf[1]);
                MMA_BF16(acc[1][2 * tnp],     af[1], bf[0], bf[1]);
                MMA_BF16(acc[0][2 * tnp + 1], af[0], bf[2], bf[3]);
                MMA_BF16(acc[1][2 * tnp + 1], af[1], bf[2], bf[3]);
            }
        }
        __syncthreads();
    }

    // epilogue: accum cols (2lr, 2lr+1) are the (a, g) GLU pair of out col tn*4+lr
    #pragma unroll
    for (int tm = 0; tm < 2; tm++) {
        const int mrow = m0 + warp_m * 32 + tm * 16 + lq;
        #pragma unroll
        for (int tn = 0; tn < 8; tn++) {
            const int col = n0 + warp_n * 32 + tn * 4 + lr;
            const float ba = bias[col], bg = bias[Hd + col];
            {
                float a = acc[tm][tn][0] + ba;
                float g = acc[tm][tn][1] + bg;
                out[(size_t)mrow * Hd + col] =
                    a / (1.0f + expf(-g)) + x[(size_t)mrow * Hd + col];
            }
            {
                float a = acc[tm][tn][2] + ba;
                float g = acc[tm][tn][3] + bg;
                out[(size_t)(mrow + 8) * Hd + col] =
                    a / (1.0f + expf(-g)) + x[(size_t)(mrow + 8) * Hd + col];
            }
        }
    }
}

// ---------------- launch ------------------------------------------------------
extern "C" void kernel_launch(void* const* d_in, const int* in_sizes, int n_in,
                              void* d_out, int out_size) {
    const float* x    = (const float*)d_in[0];   // (B, S, H)
    const float* kern = (const float*)d_in[1];   // (1, H, S)
    const float* D    = (const float*)d_in[2];   // (1, H)
    const float* W    = (const float*)d_in[3];   // (2H, H)
    const float* bias = (const float*)d_in[4];   // (2H,)
    float* out        = (float*)d_out;

    const int H  = in_sizes[2];                  // 768
    const int S  = in_sizes[1] / H;              // 8192
    const int M  = in_sizes[0] / H;              // 65536
    const int K  = H;
    const int total = M * H;

    __nv_bfloat16* act; cudaGetSymbolAddress((void**)&act, g_actb);
    __nv_bfloat16* wb;  cudaGetSymbolAddress((void**)&wb,  g_wb);

    build_taps_kernel<<<H, 256>>>(kern, S);
    conv_w_kernel<<<(2 * H * K / 4 + 255) / 256, 256>>>(W, wb, 2 * H * K / 4);
    act_kernel<<<(total / 4 + 255) / 256, 256>>>(x, D, act, total / 4, H, S);

    cudaFuncSetAttribute(gemm_glu_mma, cudaFuncAttributeMaxDynamicSharedMemorySize,
                         SMEM_GEMM);
    dim3 grid(H / CTA_C, M / CTA_M);             // (12, 256)
    gemm_glu_mma<<<grid, 512, SMEM_GEMM>>>(act, wb, bias, x, out, M, H, K);
}

// round 12
// speedup vs baseline: 6.1928x; 1.1569x over previous
#include <cuda_runtime.h>
#include <cuda_bf16.h>
#include <math.h>
#include <stdint.h>

// Problem worst-case sizing
#define MAXB 8
#define MAXS 8192
#define MAXH 768
#define MAXBS (MAXB * MAXS)          // 65536 rows

// ---------------- static device scratch ----------------
__device__ __nv_bfloat16 g_actb[(size_t)MAXBS * MAXH];      // bf16 silu activations (~100 MB)
__device__ __nv_bfloat16 g_wb[(size_t)(2 * MAXH) * MAXH];   // bf16 W (~2.4 MB)
__device__ int   g_tapPos[(size_t)MAXH * MAXS];
__device__ float g_tapVal[(size_t)MAXH * MAXS];
__device__ int   g_tapCnt[MAXH];

#define LAM 0.1f

#define CP_ASYNC16(dst, src) \
    asm volatile("cp.async.cg.shared.global [%0], [%1], 16;" :: "r"(dst), "l"(src) : "memory")

__device__ __forceinline__ uint32_t smem_u32(const void* p) {
    uint32_t a;
    asm("{ .reg .u64 t; cvta.to.shared.u64 t, %1; cvt.u32.u64 %0, t; }" : "=r"(a) : "l"(p));
    return a;
}

#define LDSM_X4(r, addr)                                                        \
    asm volatile("ldmatrix.sync.aligned.m8n8.x4.shared.b16 {%0,%1,%2,%3}, [%4];" \
        : "=r"((r)[0]), "=r"((r)[1]), "=r"((r)[2]), "=r"((r)[3]) : "r"(addr))

// mma m16n8k16 bf16, fp32 accum
#define MMA_BF16(c, a, b0, b1)                                                  \
    asm volatile(                                                               \
        "mma.sync.aligned.m16n8k16.row.col.f32.bf16.bf16.f32 "                  \
        "{%0,%1,%2,%3}, {%4,%5,%6,%7}, {%8,%9}, {%0,%1,%2,%3};"                 \
        : "+f"((c)[0]), "+f"((c)[1]), "+f"((c)[2]), "+f"((c)[3])                \
        : "r"((a)[0]), "r"((a)[1]), "r"((a)[2]), "r"((a)[3]),                   \
          "r"(b0), "r"(b1))

// ---------------- 1) threshold kernel -> sparse tap lists --------------------
__global__ void build_taps_kernel(const float* __restrict__ kern, int L) {
    int h = blockIdx.x;
    if (threadIdx.x == 0) g_tapCnt[h] = 0;
    __syncthreads();
    const float* kr = kern + (size_t)h * L;
    for (int j = threadIdx.x; j < L; j += blockDim.x) {
        float kv = kr[j];
        float a = fabsf(kv) - LAM;
        if (a > 0.0f) {
            float val = copysignf(a, kv);
            int idx = atomicAdd(&g_tapCnt[h], 1);
            g_tapPos[(size_t)h * L + idx] = j;
            g_tapVal[(size_t)h * L + idx] = val;
        }
    }
}

// ---------------- 1b) convert W to bf16 ----------------
__global__ void conv_w_kernel(const float* __restrict__ W, __nv_bfloat16* __restrict__ Wb, int n4) {
    int i = blockIdx.x * blockDim.x + threadIdx.x;
    if (i >= n4) return;
    float4 v = *(const float4*)(W + i * 4);
    __nv_bfloat162* o = (__nv_bfloat162*)(Wb + i * 4);
    o[0] = __floats2bfloat162_rn(v.x, v.y);
    o[1] = __floats2bfloat162_rn(v.z, v.w);
}

// ---------------- 2) activation: sparse conv + skip + silu -> bf16 -----------
__global__ void act_kernel(const float* __restrict__ x, const float* __restrict__ D,
                           __nv_bfloat16* __restrict__ act, int total4, int H, int S) {
    int i = blockIdx.x * blockDim.x + threadIdx.x;
    if (i >= total4) return;
    int base = i * 4;
    int h  = base % H;
    int bl = base / H;
    float4 xv = *(const float4*)(x + base);
    float4 dv = *(const float4*)(D + h);
    float v[4] = {xv.x * dv.x, xv.y * dv.y, xv.z * dv.z, xv.w * dv.w};
    int cnt[4] = {g_tapCnt[h], g_tapCnt[h + 1], g_tapCnt[h + 2], g_tapCnt[h + 3]};
    if (cnt[0] | cnt[1] | cnt[2] | cnt[3]) {
        int l = bl % S;
        int b = bl / S;
        const float* xb = x + (size_t)b * S * H;
        #pragma unroll
        for (int q = 0; q < 4; q++) {
            const int*   tp = g_tapPos + (size_t)(h + q) * S;
            const float* tv = g_tapVal + (size_t)(h + q) * S;
            for (int t = 0; t < cnt[q]; t++) {
                int j = tp[t];
                if (j <= l) v[q] += tv[t] * xb[(size_t)(l - j) * H + h + q];
            }
        }
    }
    float o0 = v[0] / (1.0f + expf(-v[0]));
    float o1 = v[1] / (1.0f + expf(-v[1]));
    float o2 = v[2] / (1.0f + expf(-v[2]));
    float o3 = v[3] / (1.0f + expf(-v[3]));
    __nv_bfloat162* op = (__nv_bfloat162*)(act + base);
    op[0] = __floats2bfloat162_rn(o0, o1);
    op[1] = __floats2bfloat162_rn(o2, o3);
}

// ---------------- 3) bf16 mma.sync GEMM + GLU + residual ---------------------
// CTA: 128 M-rows x 64 out-cols, 256 threads = 8 warps (4 m x 2 n), 2 CTAs/SM.
// B tile = 128 interleaved rows (even=Wa[n0+j/2], odd=Wg[n0+j/2]).
// K-chunk = 64 halves (128 B/row), 3-stage cp.async pipeline, 1 barrier/chunk.
#define CTA_M 128
#define CTA_C 64
#define KC    64                                   // bf16 halves per chunk
#define ABUF_BYTES (CTA_M * KC * 2)                // 16 KB
#define BBUF_BYTES (2 * CTA_C * KC * 2)            // 16 KB
#define BUF_BYTES  (ABUF_BYTES + BBUF_BYTES)       // 32 KB
#define NSTAGE 3
#define SMEM_GEMM  (NSTAGE * BUF_BYTES)            // 96 KB

__global__ __launch_bounds__(256, 2)
void gemm_glu_mma(const __nv_bfloat16* __restrict__ A, const __nv_bfloat16* __restrict__ W,
                  const float* __restrict__ bias, const float* __restrict__ x,
                  float* __restrict__ out, int M, int Hd, int K) {
    extern __shared__ char smem[];
    const uint32_t sb = smem_u32(smem);
    const int tid = threadIdx.x;
    const int wid = tid >> 5, lane = tid & 31;
    const int lq = lane >> 2, lr = lane & 3;
    const int warp_m = wid >> 1, warp_n = wid & 1;
    const int m0 = blockIdx.y * CTA_M;
    const int n0 = blockIdx.x * CTA_C;
    const int NCH = K / KC;                        // 12

    float acc[2][8][4];
    #pragma unroll
    for (int tm = 0; tm < 2; tm++)
        #pragma unroll
        for (int tn = 0; tn < 8; tn++)
            #pragma unroll
            for (int q = 0; q < 4; q++) acc[tm][tn][q] = 0.0f;

    // ldmatrix per-lane address components (16B granules, XOR-8 swizzle per row)
    const int a_rowoff = ((lane >> 3) & 1) * 8 + (lane & 7);
    const int a_gran   = lane >> 4;                // 0/1
    const int a_row    = warp_m * 32 + a_rowoff;   // + tm*16
    const uint32_t a_base0 = (uint32_t)a_row * 128;
    const int a_rsw = a_row & 7;                   // tm*16 doesn't change &7
    const int b_row  = warp_n * 64 + (lane >> 4) * 8 + (lane & 7);  // + tnp*16
    const int b_gran = (lane >> 3) & 1;
    const uint32_t b_base0 = (uint32_t)b_row * 128;
    const int b_rsw = b_row & 7;

    auto load_chunk = [&](int c, int buf) {
        const uint32_t ab = sb + buf * BUF_BYTES;
        const uint32_t bb = ab + ABUF_BYTES;
        const int k0 = c * KC;
        // A: 128 rows x 8 granules = 1024 -> 4/thread
        #pragma unroll
        for (int t = 0; t < 4; t++) {
            int idx = tid + t * 256;
            int row = idx >> 3, g = idx & 7;
            CP_ASYNC16(ab + row * 128 + ((g ^ (row & 7)) << 4),
                       A + (size_t)(m0 + row) * K + k0 + g * 8);
        }
        // B: 128 rows x 8 granules = 1024 -> 4/thread; interleaved a/g rows
        #pragma unroll
        for (int t = 0; t < 4; t++) {
            int idx = tid + t * 256;
            int row = idx >> 3, g = idx & 7;
            int wrow = ((row & 1) ? Hd : 0) + n0 + (row >> 1);
            CP_ASYNC16(bb + row * 128 + ((g ^ (row & 7)) << 4),
                       W + (size_t)wrow * K + k0 + g * 8);
        }
        asm volatile("cp.async.commit_group;" ::: "memory");
    };

    load_chunk(0, 0);
    load_chunk(1, 1);

    for (int c = 0; c < NCH; c++) {
        const int buf = c % NSTAGE;
        // chunk c is complete once <=1 newer group remains in flight
        if (c + 1 < NCH) {
            asm volatile("cp.async.wait_group 1;" ::: "memory");
        } else {
            asm volatile("cp.async.wait_group 0;" ::: "memory");
        }
        __syncthreads();
        // all threads are past compute(c-1) -> buffer (c+2)%NSTAGE is free
        if (c + 2 < NCH) load_chunk(c + 2, (c + 2) % NSTAGE);

        const uint32_t ab = sb + buf * BUF_BYTES;
        const uint32_t bb = ab + ABUF_BYTES;
        #pragma unroll
        for (int ks = 0; ks < 4; ks++) {           // 4 x k16 per chunk
            uint32_t af[2][4];
            #pragma unroll
            for (int tm = 0; tm < 2; tm++) {
                uint32_t addr = ab + a_base0 + (uint32_t)(tm * 16 * 128)
                              + (uint32_t)((((2 * ks + a_gran) ^ a_rsw)) << 4);
                LDSM_X4(af[tm], addr);
            }
            #pragma unroll
            for (int tnp = 0; tnp < 4; tnp++) {
                uint32_t bf[4];
                uint32_t addr = bb + b_base0 + (uint32_t)(tnp * 16 * 128)
                              + (uint32_t)((((2 * ks + b_gran) ^ b_rsw)) << 4);
                LDSM_X4(bf, addr);
                MMA_BF16(acc[0][2 * tnp],     af[0], bf[0], bf[1]);
                MMA_BF16(acc[1][2 * tnp],     af[1], bf[0], bf[1]);
                MMA_BF16(acc[0][2 * tnp + 1], af[0], bf[2], bf[3]);
                MMA_BF16(acc[1][2 * tnp + 1], af[1], bf[2], bf[3]);
            }
        }
    }

    // epilogue: accum cols (2lr, 2lr+1) are the (a, g) GLU pair of out col tn*4+lr
    #pragma unroll
    for (int tm = 0; tm < 2; tm++) {
        const int mrow = m0 + warp_m * 32 + tm * 16 + lq;
        #pragma unroll
        for (int tn = 0; tn < 8; tn++) {
            const int col = n0 + warp_n * 32 + tn * 4 + lr;
            const float ba = bias[col], bg = bias[Hd + col];
            {
                float a = acc[tm][tn][0] + ba;
                float g = acc[tm][tn][1] + bg;
                out[(size_t)mrow * Hd + col] =
                    a / (1.0f + expf(-g)) + x[(size_t)mrow * Hd + col];
            }
            {
                float a = acc[tm][tn][2] + ba;
                float g = acc[tm][tn][3] + bg;
                out[(size_t)(mrow + 8) * Hd + col] =
                    a / (1.0f + expf(-g)) + x[(size_t)(mrow + 8) * Hd + col];
            }
        }
    }
}

// ---------------- launch ------------------------------------------------------
extern "C" void kernel_launch(void* const* d_in, const int* in_sizes, int n_in,
                              void* d_out, int out_size) {
    const float* x    = (const float*)d_in[0];   // (B, S, H)
    const float* kern = (const float*)d_in[1];   // (1, H, S)
    const float* D    = (const float*)d_in[2];   // (1, H)
    const float* W    = (const float*)d_in[3];   // (2H, H)
    const float* bias = (const float*)d_in[4];   // (2H,)
    float* out        = (float*)d_out;

    const int H  = in_sizes[2];                  // 768
    const int S  = in_sizes[1] / H;              // 8192
    const int M  = in_sizes[0] / H;              // 65536
    const int K  = H;
    const int total = M * H;

    __nv_bfloat16* act; cudaGetSymbolAddress((void**)&act, g_actb);
    __nv_bfloat16* wb;  cudaGetSymbolAddress((void**)&wb,  g_wb);

    build_taps_kernel<<<H, 256>>>(kern, S);
    conv_w_kernel<<<(2 * H * K / 4 + 255) / 256, 256>>>(W, wb, 2 * H * K / 4);
    act_kernel<<<(total / 4 + 255) / 256, 256>>>(x, D, act, total / 4, H, S);

    cudaFuncSetAttribute(gemm_glu_mma, cudaFuncAttributeMaxDynamicSharedMemorySize,
                         SMEM_GEMM);
    dim3 grid(H / CTA_C, M / CTA_M);             // (12, 512)
    gemm_glu_mma<<<grid, 256, SMEM_GEMM>>>(act, wb, bias, x, out, M, H, K);
}

// round 13
// speedup vs baseline: 6.2785x; 1.0138x over previous
#include <cuda_runtime.h>
#include <cuda_bf16.h>
#include <math.h>
#include <stdint.h>

// Problem worst-case sizing
#define MAXB 8
#define MAXS 8192
#define MAXH 768
#define MAXBS (MAXB * MAXS)          // 65536 rows

// ---------------- static device scratch ----------------
__device__ __nv_bfloat16 g_actb[(size_t)MAXBS * MAXH];      // bf16 silu activations (~100 MB)
__device__ __nv_bfloat16 g_wb[(size_t)(2 * MAXH) * MAXH];   // bf16 W (~2.4 MB)
__device__ int   g_tapPos[(size_t)MAXH * MAXS];
__device__ float g_tapVal[(size_t)MAXH * MAXS];
__device__ int   g_tapCnt[MAXH];

#define LAM 0.1f

#define CP_ASYNC16(dst, src) \
    asm volatile("cp.async.cg.shared.global [%0], [%1], 16;" :: "r"(dst), "l"(src) : "memory")

__device__ __forceinline__ uint32_t smem_u32(const void* p) {
    uint32_t a;
    asm("{ .reg .u64 t; cvta.to.shared.u64 t, %1; cvt.u32.u64 %0, t; }" : "=r"(a) : "l"(p));
    return a;
}

#define LDSM_X4(r, addr)                                                        \
    asm volatile("ldmatrix.sync.aligned.m8n8.x4.shared.b16 {%0,%1,%2,%3}, [%4];" \
        : "=r"((r)[0]), "=r"((r)[1]), "=r"((r)[2]), "=r"((r)[3]) : "r"(addr))

// mma m16n8k16 bf16, fp32 accum
#define MMA_BF16(c, a, b0, b1)                                                  \
    asm volatile(                                                               \
        "mma.sync.aligned.m16n8k16.row.col.f32.bf16.bf16.f32 "                  \
        "{%0,%1,%2,%3}, {%4,%5,%6,%7}, {%8,%9}, {%0,%1,%2,%3};"                 \
        : "+f"((c)[0]), "+f"((c)[1]), "+f"((c)[2]), "+f"((c)[3])                \
        : "r"((a)[0]), "r"((a)[1]), "r"((a)[2]), "r"((a)[3]),                   \
          "r"(b0), "r"(b1))

// ---------------- 1) threshold kernel -> sparse tap lists --------------------
__global__ void build_taps_kernel(const float* __restrict__ kern, int L) {
    int h = blockIdx.x;
    if (threadIdx.x == 0) g_tapCnt[h] = 0;
    __syncthreads();
    const float* kr = kern + (size_t)h * L;
    for (int j = threadIdx.x; j < L; j += blockDim.x) {
        float kv = kr[j];
        float a = fabsf(kv) - LAM;
        if (a > 0.0f) {
            float val = copysignf(a, kv);
            int idx = atomicAdd(&g_tapCnt[h], 1);
            g_tapPos[(size_t)h * L + idx] = j;
            g_tapVal[(size_t)h * L + idx] = val;
        }
    }
}

// ---------------- 1b) convert W to bf16 ----------------
__global__ void conv_w_kernel(const float* __restrict__ W, __nv_bfloat16* __restrict__ Wb, int n4) {
    int i = blockIdx.x * blockDim.x + threadIdx.x;
    if (i >= n4) return;
    float4 v = *(const float4*)(W + i * 4);
    __nv_bfloat162* o = (__nv_bfloat162*)(Wb + i * 4);
    o[0] = __floats2bfloat162_rn(v.x, v.y);
    o[1] = __floats2bfloat162_rn(v.z, v.w);
}

// ---------------- 2) activation: sparse conv + skip + silu -> bf16 -----------
__global__ void act_kernel(const float* __restrict__ x, const float* __restrict__ D,
                           __nv_bfloat16* __restrict__ act, int total4, int H, int S) {
    int i = blockIdx.x * blockDim.x + threadIdx.x;
    if (i >= total4) return;
    int base = i * 4;
    int h  = base % H;
    int bl = base / H;
    float4 xv = *(const float4*)(x + base);
    float4 dv = *(const float4*)(D + h);
    float v[4] = {xv.x * dv.x, xv.y * dv.y, xv.z * dv.z, xv.w * dv.w};
    int cnt[4] = {g_tapCnt[h], g_tapCnt[h + 1], g_tapCnt[h + 2], g_tapCnt[h + 3]};
    if (cnt[0] | cnt[1] | cnt[2] | cnt[3]) {
        int l = bl % S;
        int b = bl / S;
        const float* xb = x + (size_t)b * S * H;
        #pragma unroll
        for (int q = 0; q < 4; q++) {
            const int*   tp = g_tapPos + (size_t)(h + q) * S;
            const float* tv = g_tapVal + (size_t)(h + q) * S;
            for (int t = 0; t < cnt[q]; t++) {
                int j = tp[t];
                if (j <= l) v[q] += tv[t] * xb[(size_t)(l - j) * H + h + q];
            }
        }
    }
    float o0 = v[0] / (1.0f + expf(-v[0]));
    float o1 = v[1] / (1.0f + expf(-v[1]));
    float o2 = v[2] / (1.0f + expf(-v[2]));
    float o3 = v[3] / (1.0f + expf(-v[3]));
    __nv_bfloat162* op = (__nv_bfloat162*)(act + base);
    op[0] = __floats2bfloat162_rn(o0, o1);
    op[1] = __floats2bfloat162_rn(o2, o3);
}

// ---------------- 3) bf16 mma.sync GEMM + GLU + residual ---------------------
// CTA: 128 M-rows x 64 out-cols, 256 threads = 8 warps (4 m x 2 n), 2 CTAs/SM.
// B tile = 128 interleaved rows (even=Wa[n0+j/2], odd=Wg[n0+j/2]).
// K-chunk = 64 halves, 3-stage cp.async pipeline, 1 barrier/chunk,
// register-level double buffering of A and B fragments.
#define CTA_M 128
#define CTA_C 64
#define KC    64                                   // bf16 halves per chunk
#define ABUF_BYTES (CTA_M * KC * 2)                // 16 KB
#define BBUF_BYTES (2 * CTA_C * KC * 2)            // 16 KB
#define BUF_BYTES  (ABUF_BYTES + BBUF_BYTES)       // 32 KB
#define NSTAGE 3
#define SMEM_GEMM  (NSTAGE * BUF_BYTES)            // 96 KB

__global__ __launch_bounds__(256, 2)
void gemm_glu_mma(const __nv_bfloat16* __restrict__ A, const __nv_bfloat16* __restrict__ W,
                  const float* __restrict__ bias, const float* __restrict__ x,
                  float* __restrict__ out, int M, int Hd, int K) {
    extern __shared__ char smem[];
    const uint32_t sb = smem_u32(smem);
    const int tid = threadIdx.x;
    const int wid = tid >> 5, lane = tid & 31;
    const int lq = lane >> 2, lr = lane & 3;
    const int warp_m = wid >> 1, warp_n = wid & 1;
    const int m0 = blockIdx.y * CTA_M;
    const int n0 = blockIdx.x * CTA_C;
    const int NCH = K / KC;                        // 12

    float acc[2][8][4];
    #pragma unroll
    for (int tm = 0; tm < 2; tm++)
        #pragma unroll
        for (int tn = 0; tn < 8; tn++)
            #pragma unroll
            for (int q = 0; q < 4; q++) acc[tm][tn][q] = 0.0f;

    // ldmatrix per-lane address components (16B granules, XOR-8 swizzle per row)
    const int a_rowoff = ((lane >> 3) & 1) * 8 + (lane & 7);
    const int a_gran   = lane >> 4;                // 0/1
    const int a_row    = warp_m * 32 + a_rowoff;   // + tm*16
    const uint32_t a_base0 = (uint32_t)a_row * 128;
    const int a_rsw = a_row & 7;                   // tm*16 doesn't change &7
    const int b_row  = warp_n * 64 + (lane >> 4) * 8 + (lane & 7);  // + tnp*16
    const int b_gran = (lane >> 3) & 1;
    const uint32_t b_base0 = (uint32_t)b_row * 128;
    const int b_rsw = b_row & 7;

    auto load_chunk = [&](int c, int buf) {
        const uint32_t ab = sb + buf * BUF_BYTES;
        const uint32_t bb = ab + ABUF_BYTES;
        const int k0 = c * KC;
        // A: 128 rows x 8 granules = 1024 -> 4/thread
        #pragma unroll
        for (int t = 0; t < 4; t++) {
            int idx = tid + t * 256;
            int row = idx >> 3, g = idx & 7;
            CP_ASYNC16(ab + row * 128 + ((g ^ (row & 7)) << 4),
                       A + (size_t)(m0 + row) * K + k0 + g * 8);
        }
        // B: 128 rows x 8 granules = 1024 -> 4/thread; interleaved a/g rows
        #pragma unroll
        for (int t = 0; t < 4; t++) {
            int idx = tid + t * 256;
            int row = idx >> 3, g = idx & 7;
            int wrow = ((row & 1) ? Hd : 0) + n0 + (row >> 1);
            CP_ASYNC16(bb + row * 128 + ((g ^ (row & 7)) << 4),
                       W + (size_t)wrow * K + k0 + g * 8);
        }
        asm volatile("cp.async.commit_group;" ::: "memory");
    };

    load_chunk(0, 0);
    load_chunk(1, 1);

    for (int c = 0; c < NCH; c++) {
        const int buf = c % NSTAGE;
        if (c + 1 < NCH) {
            asm volatile("cp.async.wait_group 1;" ::: "memory");
        } else {
            asm volatile("cp.async.wait_group 0;" ::: "memory");
        }
        __syncthreads();
        // all threads are past compute(c-1) -> buffer (c+2)%NSTAGE is free
        if (c + 2 < NCH) load_chunk(c + 2, (c + 2) % NSTAGE);

        const uint32_t ab = sb + buf * BUF_BYTES;
        const uint32_t bb = ab + ABUF_BYTES;

        // register double buffers
        uint32_t af[2][2][4];                      // [parity][tm][frag]
        uint32_t bf[2][4];                         // [parity][frag]

        // preload A fragments for ks=0
        #pragma unroll
        for (int tm = 0; tm < 2; tm++) {
            uint32_t addr = ab + a_base0 + (uint32_t)(tm * 16 * 128)
                          + (uint32_t)(((a_gran ^ a_rsw)) << 4);
            LDSM_X4(af[0][tm], addr);
        }

        #pragma unroll
        for (int ks = 0; ks < 4; ks++) {           // 4 x k16 per chunk
            const int cur = ks & 1, nxt = cur ^ 1;
            // prefetch next ks A fragments
            if (ks < 3) {
                #pragma unroll
                for (int tm = 0; tm < 2; tm++) {
                    uint32_t addr = ab + a_base0 + (uint32_t)(tm * 16 * 128)
                                  + (uint32_t)((((2 * (ks + 1) + a_gran) ^ a_rsw)) << 4);
                    LDSM_X4(af[nxt][tm], addr);
                }
            }
            // preload B fragment for tnp=0
            {
                uint32_t addr = bb + b_base0
                              + (uint32_t)((((2 * ks + b_gran) ^ b_rsw)) << 4);
                LDSM_X4(bf[0], addr);
            }
            #pragma unroll
            for (int tnp = 0; tnp < 4; tnp++) {
                const int bc = tnp & 1, bn = bc ^ 1;
                if (tnp < 3) {
                    uint32_t addr = bb + b_base0 + (uint32_t)((tnp + 1) * 16 * 128)
                                  + (uint32_t)((((2 * ks + b_gran) ^ b_rsw)) << 4);
                    LDSM_X4(bf[bn], addr);
                }
                MMA_BF16(acc[0][2 * tnp],     af[cur][0], bf[bc][0], bf[bc][1]);
                MMA_BF16(acc[1][2 * tnp],     af[cur][1], bf[bc][0], bf[bc][1]);
                MMA_BF16(acc[0][2 * tnp + 1], af[cur][0], bf[bc][2], bf[bc][3]);
                MMA_BF16(acc[1][2 * tnp + 1], af[cur][1], bf[bc][2], bf[bc][3]);
            }
        }
    }

    // epilogue: accum cols (2lr, 2lr+1) are the (a, g) GLU pair of out col tn*4+lr
    #pragma unroll
    for (int tm = 0; tm < 2; tm++) {
        const int mrow = m0 + warp_m * 32 + tm * 16 + lq;
        #pragma unroll
        for (int tn = 0; tn < 8; tn++) {
            const int col = n0 + warp_n * 32 + tn * 4 + lr;
            const float ba = bias[col], bg = bias[Hd + col];
            {
                float a = acc[tm][tn][0] + ba;
                float g = acc[tm][tn][1] + bg;
                out[(size_t)mrow * Hd + col] =
                    a / (1.0f + expf(-g)) + x[(size_t)mrow * Hd + col];
            }
            {
                float a = acc[tm][tn][2] + ba;
                float g = acc[tm][tn][3] + bg;
                out[(size_t)(mrow + 8) * Hd + col] =
                    a / (1.0f + expf(-g)) + x[(size_t)(mrow + 8) * Hd + col];
            }
        }
    }
}

// ---------------- launch ------------------------------------------------------
extern "C" void kernel_launch(void* const* d_in, const int* in_sizes, int n_in,
                              void* d_out, int out_size) {
    const float* x    = (const float*)d_in[0];   // (B, S, H)
    const float* kern = (const float*)d_in[1];   // (1, H, S)
    const float* D    = (const float*)d_in[2];   // (1, H)
    const float* W    = (const float*)d_in[3];   // (2H, H)
    const float* bias = (const float*)d_in[4];   // (2H,)
    float* out        = (float*)d_out;

    const int H  = in_sizes[2];                  // 768
    const int S  = in_sizes[1] / H;              // 8192
    const int M  = in_sizes[0] / H;              // 65536
    const int K  = H;
    const int total = M * H;

    __nv_bfloat16* act; cudaGetSymbolAddress((void**)&act, g_actb);
    __nv_bfloat16* wb;  cudaGetSymbolAddress((void**)&wb,  g_wb);

    build_taps_kernel<<<H, 256>>>(kern, S);
    conv_w_kernel<<<(2 * H * K / 4 + 255) / 256, 256>>>(W, wb, 2 * H * K / 4);
    act_kernel<<<(total / 4 + 255) / 256, 256>>>(x, D, act, total / 4, H, S);

    cudaFuncSetAttribute(gemm_glu_mma, cudaFuncAttributeMaxDynamicSharedMemorySize,
                         SMEM_GEMM);
    dim3 grid(H / CTA_C, M / CTA_M);             // (12, 512)
    gemm_glu_mma<<<grid, 256, SMEM_GEMM>>>(act, wb, bias, x, out, M, H, K);
}